// round 2
// baseline (speedup 1.0000x reference)
#include <cuda_runtime.h>
#include <math.h>
#include <stdint.h>

// Problem constants (fixed by setup_inputs)
#define NMAXN 200000
#define EMAXE 400000
#define GMAXG 8192
#define CMAX  256

// ---------------- scratch (static device globals; no allocation) ----------------
__device__ float g_bufA[(size_t)NMAXN * CMAX];   // x / agg buffer
__device__ float g_bufB[(size_t)NMAXN * CMAX];   // xW buffer
__device__ float g_dis[NMAXN];                   // deg -> rsqrt(deg)
__device__ float g_selfn[NMAXN];                 // 1/deg  (self-loop norm)
__device__ float g_enorm[EMAXE];
__device__ float g_pooled[(size_t)GMAXG * CMAX];
__device__ float g_cnt[GMAXG];
__device__ float g_stats[2 * CMAX];              // per-channel sum, sumsq
__device__ float g_scale[CMAX];
__device__ float g_shift[CMAX];

// ---------------- small kernels ----------------
__global__ void k_init_deg(int N) {
    int i = blockIdx.x * blockDim.x + threadIdx.x;
    if (i < N) g_dis[i] = 1.0f;   // self-loop contributes 1 to degree
}

__global__ void k_deg_accum(const int* __restrict__ dst, int E) {
    int e = blockIdx.x * blockDim.x + threadIdx.x;
    if (e < E) atomicAdd(&g_dis[dst[e]], 1.0f);
}

__global__ void k_dis_self(int N) {
    int i = blockIdx.x * blockDim.x + threadIdx.x;
    if (i < N) {
        float d = g_dis[i];          // >= 1 always (self-loop)
        g_dis[i]   = rsqrtf(d);
        g_selfn[i] = 1.0f / d;       // dis^2
    }
}

__global__ void k_enorm(const int* __restrict__ src,
                        const int* __restrict__ dst, int E) {
    int e = blockIdx.x * blockDim.x + threadIdx.x;
    if (e < E) g_enorm[e] = g_dis[src[e]] * g_dis[dst[e]];
}

// ---------------- layer 1 GEMM: [N,9] @ [9,128] ----------------
__global__ __launch_bounds__(256) void k_gemm_k9(const float* __restrict__ x,
                                                 const float* __restrict__ W,
                                                 float* __restrict__ out, int N) {
    __shared__ float Ws[9 * 128];
    int tid = threadIdx.x;
    for (int i = tid; i < 9 * 128; i += 256) Ws[i] = W[i];
    __syncthreads();
    int gid = blockIdx.x * 256 + tid;
    int row = gid >> 7;
    int c   = gid & 127;
    if (row >= N) return;
    const float* xr = x + (size_t)row * 9;
    float acc = 0.f;
#pragma unroll
    for (int k = 0; k < 9; k++) acc += xr[k] * Ws[k * 128 + c];
    out[(size_t)row * 128 + c] = acc;
}

// ---------------- generic fp32 SGEMM (A[MxK] @ B[KxN], row-major), optional bias ----------------
__global__ __launch_bounds__(256) void k_sgemm(int M, int N, int K,
                                               const float* __restrict__ A,
                                               const float* __restrict__ B,
                                               float* __restrict__ C,
                                               const float* __restrict__ bias) {
    constexpr int BM = 128, BN = 128, BK = 8, TM = 8, TN = 8;
    __shared__ __align__(16) float As[BK][BM];
    __shared__ __align__(16) float Bs[BK][BN];
    const int crow = blockIdx.y * BM;
    const int ccol = blockIdx.x * BN;
    const int tid  = threadIdx.x;
    const int tr   = (tid >> 4) * TM;
    const int tc   = (tid & 15) * TN;
    const int aRow = tid >> 1;
    const int aCol = (tid & 1) * 4;
    const int bRow = tid >> 5;
    const int bCol = (tid & 31) * 4;

    float acc[TM][TN];
#pragma unroll
    for (int i = 0; i < TM; i++)
#pragma unroll
        for (int j = 0; j < TN; j++) acc[i][j] = 0.f;

    for (int k0 = 0; k0 < K; k0 += BK) {
        float4 av;
        int gRow = crow + aRow;
        if (gRow < M) av = *(const float4*)(A + (size_t)gRow * K + k0 + aCol);
        else          av = make_float4(0.f, 0.f, 0.f, 0.f);
        As[aCol + 0][aRow] = av.x;
        As[aCol + 1][aRow] = av.y;
        As[aCol + 2][aRow] = av.z;
        As[aCol + 3][aRow] = av.w;
        float4 bv = *(const float4*)(B + (size_t)(k0 + bRow) * N + ccol + bCol);
        *(float4*)&Bs[bRow][bCol] = bv;
        __syncthreads();
#pragma unroll
        for (int k = 0; k < BK; k++) {
            float4 a0 = *(const float4*)&As[k][tr];
            float4 a1 = *(const float4*)&As[k][tr + 4];
            float4 b0 = *(const float4*)&Bs[k][tc];
            float4 b1 = *(const float4*)&Bs[k][tc + 4];
            float ra[8] = {a0.x, a0.y, a0.z, a0.w, a1.x, a1.y, a1.z, a1.w};
            float rb[8] = {b0.x, b0.y, b0.z, b0.w, b1.x, b1.y, b1.z, b1.w};
#pragma unroll
            for (int i = 0; i < TM; i++)
#pragma unroll
                for (int j = 0; j < TN; j++) acc[i][j] += ra[i] * rb[j];
        }
        __syncthreads();
    }

    float bb[TN];
#pragma unroll
    for (int j = 0; j < TN; j++) bb[j] = bias ? bias[ccol + tc + j] : 0.f;

#pragma unroll
    for (int i = 0; i < TM; i++) {
        int r = crow + tr + i;
        if (r < M) {
            float4 v0 = make_float4(acc[i][0] + bb[0], acc[i][1] + bb[1],
                                    acc[i][2] + bb[2], acc[i][3] + bb[3]);
            float4 v1 = make_float4(acc[i][4] + bb[4], acc[i][5] + bb[5],
                                    acc[i][6] + bb[6], acc[i][7] + bb[7]);
            *(float4*)&C[(size_t)r * N + ccol + tc]     = v0;
            *(float4*)&C[(size_t)r * N + ccol + tc + 4] = v1;
        }
    }
}

// ---------------- scatter: agg[dst] += enorm * h[src] ----------------
// one thread per (edge, 4 channels); tpe_shift = log2(C/4)
__global__ void k_scatter(const float* __restrict__ H, float* __restrict__ AGG,
                          const int* __restrict__ src, const int* __restrict__ dst,
                          int E, int C, int tpe_shift) {
    int gid = blockIdx.x * blockDim.x + threadIdx.x;
    int e   = gid >> tpe_shift;
    if (e >= E) return;
    int c4  = gid & ((1 << tpe_shift) - 1);
    float w = g_enorm[e];
    int s = src[e], d = dst[e];
    float4 v = *(const float4*)(H + (size_t)s * C + c4 * 4);
    float* out = AGG + (size_t)d * C + c4 * 4;
    atomicAdd(out + 0, v.x * w);
    atomicAdd(out + 1, v.y * w);
    atomicAdd(out + 2, v.z * w);
    atomicAdd(out + 3, v.w * w);
}

// ---------------- fused self-loop add + BN statistics ----------------
// blockDim.x == C; rows strided by gridDim
__global__ void k_stats_self(float* __restrict__ AGG, const float* __restrict__ H,
                             int N, int C) {
    int c = threadIdx.x;
    float s = 0.f, sq = 0.f;
    for (int i = blockIdx.x; i < N; i += gridDim.x) {
        size_t off = (size_t)i * C + c;
        float v = AGG[off] + g_selfn[i] * H[off];
        AGG[off] = v;
        s  += v;
        sq += v * v;
    }
    atomicAdd(&g_stats[c], s);
    atomicAdd(&g_stats[C + c], sq);
}

__global__ void k_finalize_stats(const float* __restrict__ gamma,
                                 const float* __restrict__ beta, int N, int C) {
    int c = threadIdx.x;
    if (c < C) {
        float invN = 1.0f / (float)N;
        float mean = g_stats[c] * invN;
        float var  = g_stats[C + c] * invN - mean * mean;
        float sc   = gamma[c] * rsqrtf(var + 1e-5f);
        g_scale[c] = sc;
        g_shift[c] = beta[c] - mean * sc;
    }
}

// y = relu(x*scale + shift), in place, float4
__global__ void k_bn_relu(float* __restrict__ A, int total4, int c4mask) {
    int idx = blockIdx.x * blockDim.x + threadIdx.x;
    if (idx >= total4) return;
    int c4 = idx & c4mask;
    float4 v  = ((float4*)A)[idx];
    float4 sc = ((const float4*)g_scale)[c4];
    float4 sh = ((const float4*)g_shift)[c4];
    v.x = fmaxf(0.f, v.x * sc.x + sh.x);
    v.y = fmaxf(0.f, v.y * sc.y + sh.y);
    v.z = fmaxf(0.f, v.z * sc.z + sh.z);
    v.w = fmaxf(0.f, v.w * sc.w + sh.w);
    ((float4*)A)[idx] = v;
}

// ---------------- global mean pool ----------------
__global__ void k_pool_accum(const float* __restrict__ A,
                             const int* __restrict__ batch, int N) {
    int gid = blockIdx.x * blockDim.x + threadIdx.x;
    int i   = gid >> 6;          // 64 float4-threads per row (C=256)
    if (i >= N) return;
    int c4 = gid & 63;
    int b  = batch[i];
    float4 v = *(const float4*)(A + (size_t)i * 256 + c4 * 4);
    float* out = g_pooled + (size_t)b * 256 + c4 * 4;
    atomicAdd(out + 0, v.x);
    atomicAdd(out + 1, v.y);
    atomicAdd(out + 2, v.z);
    atomicAdd(out + 3, v.w);
    if (c4 == 0) atomicAdd(&g_cnt[b], 1.0f);
}

__global__ void k_pool_div(int G) {
    int idx = blockIdx.x * blockDim.x + threadIdx.x;
    if (idx >= G * 256) return;
    int g = idx >> 8;
    g_pooled[idx] *= (1.0f / fmaxf(g_cnt[g], 1.0f));
}

// ---------------- host launcher ----------------
extern "C" void kernel_launch(void* const* d_in, const int* in_sizes, int n_in,
                              void* d_out, int out_size) {
    const float* x     = (const float*)d_in[0];
    const int*   ei    = (const int*)d_in[1];     // int32 (jax x64 disabled)
    const int*   batch = (const int*)d_in[2];     // int32
    const float* W1  = (const float*)d_in[4];
    const float* g1  = (const float*)d_in[6];
    const float* be1 = (const float*)d_in[7];
    const float* W2  = (const float*)d_in[8];
    const float* g2  = (const float*)d_in[10];
    const float* be2 = (const float*)d_in[11];
    const float* W3  = (const float*)d_in[12];
    const float* g3  = (const float*)d_in[14];
    const float* be3 = (const float*)d_in[15];
    const float* Wp  = (const float*)d_in[16];
    const float* bp  = (const float*)d_in[17];
    float* out = (float*)d_out;

    const int N = in_sizes[0] / 9;
    const int E = in_sizes[1] / 2;
    const int G = out_size / 256;

    void *pA, *pB, *pPooled, *pCnt, *pStats;
    cudaGetSymbolAddress(&pA, g_bufA);
    cudaGetSymbolAddress(&pB, g_bufB);
    cudaGetSymbolAddress(&pPooled, g_pooled);
    cudaGetSymbolAddress(&pCnt, g_cnt);
    cudaGetSymbolAddress(&pStats, g_stats);
    float* bufA = (float*)pA;
    float* bufB = (float*)pB;

    const int* src = ei;
    const int* dst = ei + E;

    // ---- degree / normalization prep ----
    k_init_deg<<<(N + 255) / 256, 256>>>(N);
    k_deg_accum<<<(E + 255) / 256, 256>>>(dst, E);
    k_dis_self<<<(N + 255) / 256, 256>>>(N);
    k_enorm<<<(E + 255) / 256, 256>>>(src, dst, E);

    // ---- Layer 1: [N,9] -> [N,128] ----
    {
        const int C = 128;
        k_gemm_k9<<<(N * 128 + 255) / 256, 256>>>(x, W1, bufB, N);
        cudaMemsetAsync(bufA, 0, (size_t)N * C * sizeof(float), 0);
        cudaMemsetAsync(pStats, 0, 2 * C * sizeof(float), 0);
        int tot = E * (C / 4);
        k_scatter<<<(tot + 255) / 256, 256>>>(bufB, bufA, src, dst, E, C, 5);
        k_stats_self<<<2048, C>>>(bufA, bufB, N, C);
        k_finalize_stats<<<1, C>>>(g1, be1, N, C);
        int t4 = N * C / 4;
        k_bn_relu<<<(t4 + 255) / 256, 256>>>(bufA, t4, C / 4 - 1);
    }

    // ---- Layer 2: [N,128] -> [N,256] ----
    {
        const int C = 256;
        dim3 grid(C / 128, (N + 127) / 128);
        k_sgemm<<<grid, 256>>>(N, C, 128, bufA, W2, bufB, nullptr);
        cudaMemsetAsync(bufA, 0, (size_t)N * C * sizeof(float), 0);
        cudaMemsetAsync(pStats, 0, 2 * C * sizeof(float), 0);
        int tot = E * (C / 4);
        k_scatter<<<(tot + 255) / 256, 256>>>(bufB, bufA, src, dst, E, C, 6);
        k_stats_self<<<2048, C>>>(bufA, bufB, N, C);
        k_finalize_stats<<<1, C>>>(g2, be2, N, C);
        int t4 = N * C / 4;
        k_bn_relu<<<(t4 + 255) / 256, 256>>>(bufA, t4, C / 4 - 1);
    }

    // ---- Layer 3: [N,256] -> [N,256] ----
    {
        const int C = 256;
        dim3 grid(C / 128, (N + 127) / 128);
        k_sgemm<<<grid, 256>>>(N, C, 256, bufA, W3, bufB, nullptr);
        cudaMemsetAsync(bufA, 0, (size_t)N * C * sizeof(float), 0);
        cudaMemsetAsync(pStats, 0, 2 * C * sizeof(float), 0);
        int tot = E * (C / 4);
        k_scatter<<<(tot + 255) / 256, 256>>>(bufB, bufA, src, dst, E, C, 6);
        k_stats_self<<<2048, C>>>(bufA, bufB, N, C);
        k_finalize_stats<<<1, C>>>(g3, be3, N, C);
        int t4 = N * C / 4;
        k_bn_relu<<<(t4 + 255) / 256, 256>>>(bufA, t4, C / 4 - 1);
    }

    // ---- global mean pool ----
    cudaMemsetAsync(pPooled, 0, (size_t)G * 256 * sizeof(float), 0);
    cudaMemsetAsync(pCnt, 0, G * sizeof(float), 0);
    {
        int tot = N * 64;
        k_pool_accum<<<(tot + 255) / 256, 256>>>(bufA, batch, N);
        k_pool_div<<<(G * 256 + 255) / 256, 256>>>(G);
    }

    // ---- final linear: [G,256] @ [256,256] + bp ----
    {
        dim3 grid(256 / 128, (G + 127) / 128);
        k_sgemm<<<grid, 256>>>(G, 256, 256, (float*)pPooled, Wp, out, bp);
    }
}

// round 3
// speedup vs baseline: 1.8862x; 1.8862x over previous
#include <cuda_runtime.h>
#include <math.h>
#include <stdint.h>

#define NMAXN 200000
#define EMAXE 400000
#define GMAXG 8192
#define CMAX  256
#define SCAN_NB 1024   // max blocks for scan level-2 (N/256 = 782 <= 1024)

// ---------------- scratch (static device globals; no allocation) ----------------
__device__ float g_bufA[(size_t)NMAXN * CMAX];   // agg buffer
__device__ float g_bufB[(size_t)NMAXN * CMAX];   // xW buffer
__device__ float g_dis[NMAXN];                   // rsqrt(deg)
__device__ float g_selfn[NMAXN];                 // 1/deg (self-loop weight)
__device__ int   g_degi[NMAXN];
__device__ int   g_rowStart[NMAXN + 1];
__device__ int   g_blkSum[SCAN_NB];
__device__ int   g_fill[NMAXN];
__device__ int   g_csr_src[EMAXE];
__device__ float g_csr_w[EMAXE];
__device__ float g_pooled[(size_t)GMAXG * CMAX];
__device__ float g_stats[2 * CMAX];
__device__ float g_scale[CMAX];
__device__ float g_shift[CMAX];

// ---------------- prep ----------------
__global__ void k_deg_accum(const int* __restrict__ dst, int E) {
    int e = blockIdx.x * blockDim.x + threadIdx.x;
    if (e < E) atomicAdd(&g_degi[dst[e]], 1);
}

__global__ void k_dis_self(int N) {
    int i = blockIdx.x * blockDim.x + threadIdx.x;
    if (i < N) {
        float d = (float)(g_degi[i] + 1);   // +1 self-loop
        g_dis[i]   = rsqrtf(d);
        g_selfn[i] = 1.0f / d;
    }
}

// 2-level exclusive scan of g_degi -> g_rowStart
__global__ void k_scan1(int N) {
    __shared__ int sh[256];
    int i = blockIdx.x * 256 + threadIdx.x;
    int v = (i < N) ? g_degi[i] : 0;
    sh[threadIdx.x] = v;
    __syncthreads();
    for (int off = 1; off < 256; off <<= 1) {
        int t = (threadIdx.x >= off) ? sh[threadIdx.x - off] : 0;
        __syncthreads();
        sh[threadIdx.x] += t;
        __syncthreads();
    }
    if (i < N) g_rowStart[i] = sh[threadIdx.x] - v;   // block-local exclusive
    if (threadIdx.x == 255) g_blkSum[blockIdx.x] = sh[255];
}

__global__ void k_scan2(int NB) {
    __shared__ int sh[SCAN_NB];
    int v = (threadIdx.x < NB) ? g_blkSum[threadIdx.x] : 0;
    sh[threadIdx.x] = v;
    __syncthreads();
    for (int off = 1; off < SCAN_NB; off <<= 1) {
        int t = ((int)threadIdx.x >= off) ? sh[threadIdx.x - off] : 0;
        __syncthreads();
        sh[threadIdx.x] += t;
        __syncthreads();
    }
    if (threadIdx.x < NB) g_blkSum[threadIdx.x] = sh[threadIdx.x] - v;  // exclusive
}

__global__ void k_scan3(int N, int E) {
    int i = blockIdx.x * blockDim.x + threadIdx.x;
    if (i < N) g_rowStart[i] += g_blkSum[i >> 8];
    if (i == 0) g_rowStart[N] = E;
}

__global__ void k_csr_fill(const int* __restrict__ src, const int* __restrict__ dst, int E) {
    int e = blockIdx.x * blockDim.x + threadIdx.x;
    if (e < E) {
        int s = src[e], d = dst[e];
        int pos = g_rowStart[d] + atomicAdd(&g_fill[d], 1);
        g_csr_src[pos] = s;
        g_csr_w[pos]   = g_dis[s] * g_dis[d];
    }
}

// ---------------- layer 1 GEMM: [N,9] @ [9,128] ----------------
__global__ __launch_bounds__(256) void k_gemm_k9(const float* __restrict__ x,
                                                 const float* __restrict__ W,
                                                 float* __restrict__ out, int N) {
    __shared__ float Ws[9 * 128];
    int tid = threadIdx.x;
    for (int i = tid; i < 9 * 128; i += 256) Ws[i] = W[i];
    __syncthreads();
    int gid = blockIdx.x * 256 + tid;
    int row = gid >> 7;
    int c   = gid & 127;
    if (row >= N) return;
    const float* xr = x + (size_t)row * 9;
    float acc = 0.f;
#pragma unroll
    for (int k = 0; k < 9; k++) acc += xr[k] * Ws[k * 128 + c];
    out[(size_t)row * 128 + c] = acc;
}

// ---------------- fp32 SGEMM with optional fused BN+ReLU on A, optional bias ----------------
__global__ __launch_bounds__(256) void k_sgemm(int M, int N, int K,
                                               const float* __restrict__ A,
                                               const float* __restrict__ B,
                                               float* __restrict__ C,
                                               const float* __restrict__ bias,
                                               const float* __restrict__ bnScale,
                                               const float* __restrict__ bnShift) {
    constexpr int BM = 128, BN = 128, BK = 8, TM = 8, TN = 8;
    __shared__ __align__(16) float As[BK][BM];
    __shared__ __align__(16) float Bs[BK][BN];
    const int crow = blockIdx.y * BM;
    const int ccol = blockIdx.x * BN;
    const int tid  = threadIdx.x;
    const int tr   = (tid >> 4) * TM;
    const int tc   = (tid & 15) * TN;
    const int aRow = tid >> 1;
    const int aCol = (tid & 1) * 4;
    const int bRow = tid >> 5;
    const int bCol = (tid & 31) * 4;

    float acc[TM][TN];
#pragma unroll
    for (int i = 0; i < TM; i++)
#pragma unroll
        for (int j = 0; j < TN; j++) acc[i][j] = 0.f;

    for (int k0 = 0; k0 < K; k0 += BK) {
        float4 av;
        int gRow = crow + aRow;
        if (gRow < M) av = *(const float4*)(A + (size_t)gRow * K + k0 + aCol);
        else          av = make_float4(0.f, 0.f, 0.f, 0.f);
        if (bnScale) {
            int kc = k0 + aCol;
            av.x = fmaxf(0.f, av.x * bnScale[kc + 0] + bnShift[kc + 0]);
            av.y = fmaxf(0.f, av.y * bnScale[kc + 1] + bnShift[kc + 1]);
            av.z = fmaxf(0.f, av.z * bnScale[kc + 2] + bnShift[kc + 2]);
            av.w = fmaxf(0.f, av.w * bnScale[kc + 3] + bnShift[kc + 3]);
        }
        As[aCol + 0][aRow] = av.x;
        As[aCol + 1][aRow] = av.y;
        As[aCol + 2][aRow] = av.z;
        As[aCol + 3][aRow] = av.w;
        float4 bv = *(const float4*)(B + (size_t)(k0 + bRow) * N + ccol + bCol);
        *(float4*)&Bs[bRow][bCol] = bv;
        __syncthreads();
#pragma unroll
        for (int k = 0; k < BK; k++) {
            float4 a0 = *(const float4*)&As[k][tr];
            float4 a1 = *(const float4*)&As[k][tr + 4];
            float4 b0 = *(const float4*)&Bs[k][tc];
            float4 b1 = *(const float4*)&Bs[k][tc + 4];
            float ra[8] = {a0.x, a0.y, a0.z, a0.w, a1.x, a1.y, a1.z, a1.w};
            float rb[8] = {b0.x, b0.y, b0.z, b0.w, b1.x, b1.y, b1.z, b1.w};
#pragma unroll
            for (int i = 0; i < TM; i++)
#pragma unroll
                for (int j = 0; j < TN; j++) acc[i][j] += ra[i] * rb[j];
        }
        __syncthreads();
    }

    float bb[TN];
#pragma unroll
    for (int j = 0; j < TN; j++) bb[j] = bias ? bias[ccol + tc + j] : 0.f;

#pragma unroll
    for (int i = 0; i < TM; i++) {
        int r = crow + tr + i;
        if (r < M) {
            float4 v0 = make_float4(acc[i][0] + bb[0], acc[i][1] + bb[1],
                                    acc[i][2] + bb[2], acc[i][3] + bb[3]);
            float4 v1 = make_float4(acc[i][4] + bb[4], acc[i][5] + bb[5],
                                    acc[i][6] + bb[6], acc[i][7] + bb[7]);
            *(float4*)&C[(size_t)r * N + ccol + tc]     = v0;
            *(float4*)&C[(size_t)r * N + ccol + tc + 4] = v1;
        }
    }
}

// ---------------- CSR gather + self-loop + BN statistics (fused) ----------------
// blockDim.x == C; grid-stride over nodes
__global__ void k_gather_stats(const float* __restrict__ H, float* __restrict__ AGG,
                               int N, int C) {
    int c = threadIdx.x;
    float s = 0.f, sq = 0.f;
    for (int i = blockIdx.x; i < N; i += gridDim.x) {
        int st = g_rowStart[i];
        int en = g_rowStart[i + 1];
        float acc = g_selfn[i] * H[(size_t)i * C + c];
        for (int j = st; j < en; j++) {
            int sn = g_csr_src[j];
            acc += g_csr_w[j] * H[(size_t)sn * C + c];
        }
        AGG[(size_t)i * C + c] = acc;
        s  += acc;
        sq += acc * acc;
    }
    atomicAdd(&g_stats[c], s);
    atomicAdd(&g_stats[C + c], sq);
}

__global__ void k_finalize_stats(const float* __restrict__ gamma,
                                 const float* __restrict__ beta, int N, int C) {
    int c = threadIdx.x;
    if (c < C) {
        float invN = 1.0f / (float)N;
        float mean = g_stats[c] * invN;
        float var  = g_stats[C + c] * invN - mean * mean;
        float sc   = gamma[c] * rsqrtf(var + 1e-5f);
        g_scale[c] = sc;
        g_shift[c] = beta[c] - mean * sc;
    }
}

// ---------------- pool with fused BN+ReLU (batch is sorted) ----------------
__global__ void k_pool(const float* __restrict__ AGG, const int* __restrict__ batch,
                       int N, int G) {
    int g = blockIdx.x;
    int c = threadIdx.x;          // 256
    __shared__ int s_lo, s_hi;
    if (c == 0) {
        int lo = 0, hi = N;
        while (lo < hi) { int m = (lo + hi) >> 1; if (batch[m] < g) lo = m + 1; else hi = m; }
        s_lo = lo;
        int lo2 = lo, hi2 = N;
        while (lo2 < hi2) { int m = (lo2 + hi2) >> 1; if (batch[m] <= g) lo2 = m + 1; else hi2 = m; }
        s_hi = lo2;
    }
    __syncthreads();
    float sc = g_scale[c], sh = g_shift[c];
    float sum = 0.f;
    for (int i = s_lo; i < s_hi; i++)
        sum += fmaxf(0.f, AGG[(size_t)i * 256 + c] * sc + sh);
    int cnt = s_hi - s_lo;
    g_pooled[(size_t)g * 256 + c] = sum / fmaxf((float)cnt, 1.0f);
}

// ---------------- host launcher ----------------
extern "C" void kernel_launch(void* const* d_in, const int* in_sizes, int n_in,
                              void* d_out, int out_size) {
    const float* x     = (const float*)d_in[0];
    const int*   ei    = (const int*)d_in[1];
    const int*   batch = (const int*)d_in[2];
    const float* W1  = (const float*)d_in[4];
    const float* g1  = (const float*)d_in[6];
    const float* be1 = (const float*)d_in[7];
    const float* W2  = (const float*)d_in[8];
    const float* g2  = (const float*)d_in[10];
    const float* be2 = (const float*)d_in[11];
    const float* W3  = (const float*)d_in[12];
    const float* g3  = (const float*)d_in[14];
    const float* be3 = (const float*)d_in[15];
    const float* Wp  = (const float*)d_in[16];
    const float* bp  = (const float*)d_in[17];
    float* out = (float*)d_out;

    const int N = in_sizes[0] / 9;
    const int E = in_sizes[1] / 2;
    const int G = out_size / 256;
    const int NB = (N + 255) / 256;

    void *pA, *pB, *pPooled, *pStats, *pDegi, *pFill, *pScale, *pShift;
    cudaGetSymbolAddress(&pA, g_bufA);
    cudaGetSymbolAddress(&pB, g_bufB);
    cudaGetSymbolAddress(&pPooled, g_pooled);
    cudaGetSymbolAddress(&pStats, g_stats);
    cudaGetSymbolAddress(&pDegi, g_degi);
    cudaGetSymbolAddress(&pFill, g_fill);
    cudaGetSymbolAddress(&pScale, g_scale);
    cudaGetSymbolAddress(&pShift, g_shift);
    float* bufA = (float*)pA;
    float* bufB = (float*)pB;
    const float* dScale = (const float*)pScale;
    const float* dShift = (const float*)pShift;

    const int* src = ei;
    const int* dst = ei + E;

    // ---- degree + CSR build ----
    cudaMemsetAsync(pDegi, 0, N * sizeof(int), 0);
    cudaMemsetAsync(pFill, 0, N * sizeof(int), 0);
    k_deg_accum<<<(E + 255) / 256, 256>>>(dst, E);
    k_dis_self<<<(N + 255) / 256, 256>>>(N);
    k_scan1<<<NB, 256>>>(N);
    k_scan2<<<1, SCAN_NB>>>(NB);
    k_scan3<<<NB, 256>>>(N, E);
    k_csr_fill<<<(E + 255) / 256, 256>>>(src, dst, E);

    // ---- Layer 1: [N,9] -> [N,128] ----
    k_gemm_k9<<<(N * 128 + 255) / 256, 256>>>(x, W1, bufB, N);
    cudaMemsetAsync(pStats, 0, 2 * 128 * sizeof(float), 0);
    k_gather_stats<<<2048, 128>>>(bufB, bufA, N, 128);
    k_finalize_stats<<<1, 128>>>(g1, be1, N, 128);

    // ---- Layer 2: bn_relu(agg1) @ W2 -> [N,256] ----
    {
        dim3 grid(256 / 128, (N + 127) / 128);
        k_sgemm<<<grid, 256>>>(N, 256, 128, bufA, W2, bufB, nullptr, dScale, dShift);
        cudaMemsetAsync(pStats, 0, 2 * 256 * sizeof(float), 0);
        k_gather_stats<<<2048, 256>>>(bufB, bufA, N, 256);
        k_finalize_stats<<<1, 256>>>(g2, be2, N, 256);
    }

    // ---- Layer 3: bn_relu(agg2) @ W3 -> [N,256] ----
    {
        dim3 grid(256 / 128, (N + 127) / 128);
        k_sgemm<<<grid, 256>>>(N, 256, 256, bufA, W3, bufB, nullptr, dScale, dShift);
        cudaMemsetAsync(pStats, 0, 2 * 256 * sizeof(float), 0);
        k_gather_stats<<<2048, 256>>>(bufB, bufA, N, 256);
        k_finalize_stats<<<1, 256>>>(g3, be3, N, 256);
    }

    // ---- pool (fused BN3+ReLU) + final linear ----
    k_pool<<<G, 256>>>(bufA, batch, N, G);
    {
        dim3 grid(256 / 128, (G + 127) / 128);
        k_sgemm<<<grid, 256>>>(G, 256, 256, (float*)pPooled, Wp, out, bp, nullptr, nullptr);
    }
}

// round 5
// speedup vs baseline: 2.7743x; 1.4708x over previous
#include <cuda_runtime.h>
#include <math.h>
#include <stdint.h>

#define NMAXN 200000
#define EMAXE 400000
#define GMAXG 8192
#define CMAX  256
#define SCAN_NB 1024

// ---------------- scratch (static device globals; no allocation) ----------------
__device__ float g_bufA[(size_t)NMAXN * CMAX];
__device__ float g_bufB[(size_t)NMAXN * CMAX];
__device__ float g_dis[NMAXN];
__device__ float g_selfn[NMAXN];
__device__ int   g_degi[NMAXN];
__device__ int   g_rowStart[NMAXN + 1];
__device__ int   g_blkSum[SCAN_NB];
__device__ int   g_fill[NMAXN];
__device__ int   g_csr_src[EMAXE];
__device__ float g_csr_w[EMAXE];
__device__ float g_pooled[(size_t)GMAXG * CMAX];
__device__ float g_stats[2 * CMAX];
__device__ float g_scale[CMAX];
__device__ float g_shift[CMAX];
__device__ float g_Wt2[128 * 256];
__device__ float g_Wt3[256 * 256];
__device__ float g_Wtp[256 * 256];

// ---------------- helpers ----------------
__device__ __forceinline__ float tf32r(float x) {
    uint32_t u;
    asm("cvt.rna.tf32.f32 %0, %1;" : "=r"(u) : "f"(x));
    return __uint_as_float(u);
}
__device__ __forceinline__ void mma_tf32(float d[4], const uint32_t a[4], const uint32_t b[2]) {
    asm volatile(
        "mma.sync.aligned.m16n8k8.row.col.f32.tf32.tf32.f32 "
        "{%0,%1,%2,%3}, {%4,%5,%6,%7}, {%8,%9}, {%0,%1,%2,%3};"
        : "+f"(d[0]), "+f"(d[1]), "+f"(d[2]), "+f"(d[3])
        : "r"(a[0]), "r"(a[1]), "r"(a[2]), "r"(a[3]), "r"(b[0]), "r"(b[1]));
}

// ---------------- prep ----------------
__global__ void k_deg_accum(const int* __restrict__ dst, int E) {
    int e = blockIdx.x * blockDim.x + threadIdx.x;
    if (e < E) atomicAdd(&g_degi[dst[e]], 1);
}
__global__ void k_dis_self(int N) {
    int i = blockIdx.x * blockDim.x + threadIdx.x;
    if (i < N) {
        float d = (float)(g_degi[i] + 1);
        g_dis[i] = rsqrtf(d);
        g_selfn[i] = 1.0f / d;
    }
}
__global__ void k_scan1(int N) {
    __shared__ int sh[256];
    int i = blockIdx.x * 256 + threadIdx.x;
    int v = (i < N) ? g_degi[i] : 0;
    sh[threadIdx.x] = v;
    __syncthreads();
    for (int off = 1; off < 256; off <<= 1) {
        int t = (threadIdx.x >= off) ? sh[threadIdx.x - off] : 0;
        __syncthreads();
        sh[threadIdx.x] += t;
        __syncthreads();
    }
    if (i < N) g_rowStart[i] = sh[threadIdx.x] - v;
    if (threadIdx.x == 255) g_blkSum[blockIdx.x] = sh[255];
}
__global__ void k_scan2(int NB) {
    __shared__ int sh[SCAN_NB];
    int v = ((int)threadIdx.x < NB) ? g_blkSum[threadIdx.x] : 0;
    sh[threadIdx.x] = v;
    __syncthreads();
    for (int off = 1; off < SCAN_NB; off <<= 1) {
        int t = ((int)threadIdx.x >= off) ? sh[threadIdx.x - off] : 0;
        __syncthreads();
        sh[threadIdx.x] += t;
        __syncthreads();
    }
    if ((int)threadIdx.x < NB) g_blkSum[threadIdx.x] = sh[threadIdx.x] - v;
}
__global__ void k_scan3(int N, int E) {
    int i = blockIdx.x * blockDim.x + threadIdx.x;
    if (i < N) g_rowStart[i] += g_blkSum[i >> 8];
    if (i == 0) g_rowStart[N] = E;
}
__global__ void k_csr_fill(const int* __restrict__ src, const int* __restrict__ dst, int E) {
    int e = blockIdx.x * blockDim.x + threadIdx.x;
    if (e < E) {
        int s = src[e], d = dst[e];
        int pos = g_rowStart[d] + atomicAdd(&g_fill[d], 1);
        g_csr_src[pos] = s;
        g_csr_w[pos]   = g_dis[s] * g_dis[d];
    }
}
__global__ void k_transpose(const float* __restrict__ W, float* __restrict__ Wt,
                            int K, int N) {
    int idx = blockIdx.x * blockDim.x + threadIdx.x;
    if (idx < K * N) {
        int k = idx / N, n = idx % N;
        Wt[(size_t)n * K + k] = W[idx];
    }
}

// ---------------- layer 1 GEMM: [N,9] @ [9,128] ----------------
__global__ __launch_bounds__(256) void k_gemm_k9(const float* __restrict__ x,
                                                 const float* __restrict__ W,
                                                 float* __restrict__ out, int N) {
    __shared__ float Ws[9 * 128];
    int tid = threadIdx.x;
    for (int i = tid; i < 9 * 128; i += 256) Ws[i] = W[i];
    __syncthreads();
    int gid = blockIdx.x * 256 + tid;
    int row = gid >> 7;
    int c   = gid & 127;
    if (row >= N) return;
    const float* xr = x + (size_t)row * 9;
    float acc = 0.f;
#pragma unroll
    for (int k = 0; k < 9; k++) acc += xr[k] * Ws[k * 128 + c];
    out[(size_t)row * 128 + c] = acc;
}

// ---------------- tf32 mma.sync GEMM ----------------
// C[M, Ncols] = op(A)[M,K] @ Wt^T  where Wt is [Ncols, K] row-major.
// op(A) = relu(A*bnS + bnB) if bnS != nullptr. bias added to C if bias != nullptr.
// CTA: 128x128 tile, BK=32, 8 warps (2 x 4), warp tile 64x32 (m16n8k8 frags 4x4).
__global__ __launch_bounds__(256, 2) void k_mma(const float* __restrict__ A,
                                                const float* __restrict__ Wt,
                                                float* __restrict__ C,
                                                int M, int K, int Ncols,
                                                const float* __restrict__ bias,
                                                const float* __restrict__ bnS,
                                                const float* __restrict__ bnB) {
    __shared__ float As[128][36];
    __shared__ float Bs[128][36];
    const int tid  = threadIdx.x;
    const int wid  = tid >> 5;
    const int lane = tid & 31;
    const int wr   = (wid & 1) * 64;    // warp row offset in tile
    const int wc   = (wid >> 1) * 32;   // warp col offset in tile
    const int row0 = blockIdx.y * 128;
    const int col0 = blockIdx.x * 128;
    const int gq   = lane >> 2;         // group id 0..7
    const int tq   = lane & 3;          // thread-in-group 0..3

    float acc[4][4][4];
#pragma unroll
    for (int mt = 0; mt < 4; mt++)
#pragma unroll
        for (int nt = 0; nt < 4; nt++)
#pragma unroll
            for (int q = 0; q < 4; q++) acc[mt][nt][q] = 0.f;

    for (int k0 = 0; k0 < K; k0 += 32) {
        // ---- stage A tile: 128 rows x 32 k (1024 float4) ----
#pragma unroll
        for (int i = 0; i < 4; i++) {
            int idx = tid + i * 256;
            int r = idx >> 3, j = (idx & 7) * 4;
            float4 v = make_float4(0.f, 0.f, 0.f, 0.f);
            int gr = row0 + r;
            if (gr < M) {
                v = *(const float4*)(A + (size_t)gr * K + k0 + j);
                if (bnS) {
                    float4 sc = *(const float4*)(bnS + k0 + j);
                    float4 sh = *(const float4*)(bnB + k0 + j);
                    v.x = fmaxf(0.f, v.x * sc.x + sh.x);
                    v.y = fmaxf(0.f, v.y * sc.y + sh.y);
                    v.z = fmaxf(0.f, v.z * sc.z + sh.z);
                    v.w = fmaxf(0.f, v.w * sc.w + sh.w);
                }
            }
            v.x = tf32r(v.x); v.y = tf32r(v.y); v.z = tf32r(v.z); v.w = tf32r(v.w);
            *(float4*)&As[r][j] = v;
        }
        // ---- stage B tile: 128 n-rows x 32 k ----
#pragma unroll
        for (int i = 0; i < 4; i++) {
            int idx = tid + i * 256;
            int n = idx >> 3, j = (idx & 7) * 4;
            float4 v = *(const float4*)(Wt + (size_t)(col0 + n) * K + k0 + j);
            v.x = tf32r(v.x); v.y = tf32r(v.y); v.z = tf32r(v.z); v.w = tf32r(v.w);
            *(float4*)&Bs[n][j] = v;
        }
        __syncthreads();

#pragma unroll
        for (int kk = 0; kk < 4; kk++) {
            uint32_t af[4][4], bf[4][2];
#pragma unroll
            for (int mt = 0; mt < 4; mt++) {
                int r = wr + mt * 16 + gq;
                af[mt][0] = __float_as_uint(As[r][kk * 8 + tq]);
                af[mt][1] = __float_as_uint(As[r + 8][kk * 8 + tq]);
                af[mt][2] = __float_as_uint(As[r][kk * 8 + 4 + tq]);
                af[mt][3] = __float_as_uint(As[r + 8][kk * 8 + 4 + tq]);
            }
#pragma unroll
            for (int nt = 0; nt < 4; nt++) {
                int n = wc + nt * 8 + gq;
                bf[nt][0] = __float_as_uint(Bs[n][kk * 8 + tq]);
                bf[nt][1] = __float_as_uint(Bs[n][kk * 8 + 4 + tq]);
            }
#pragma unroll
            for (int mt = 0; mt < 4; mt++)
#pragma unroll
                for (int nt = 0; nt < 4; nt++)
                    mma_tf32(acc[mt][nt], af[mt], bf[nt]);
        }
        __syncthreads();
    }

    // ---- epilogue ----
#pragma unroll
    for (int mt = 0; mt < 4; mt++) {
        int r0 = row0 + wr + mt * 16 + gq;
        int r1 = r0 + 8;
#pragma unroll
        for (int nt = 0; nt < 4; nt++) {
            int c = col0 + wc + nt * 8 + tq * 2;
            float b0 = 0.f, b1 = 0.f;
            if (bias) { b0 = bias[c]; b1 = bias[c + 1]; }
            if (r0 < M) {
                float2 v = make_float2(acc[mt][nt][0] + b0, acc[mt][nt][1] + b1);
                *(float2*)(C + (size_t)r0 * Ncols + c) = v;
            }
            if (r1 < M) {
                float2 v = make_float2(acc[mt][nt][2] + b0, acc[mt][nt][3] + b1);
                *(float2*)(C + (size_t)r1 * Ncols + c) = v;
            }
        }
    }
}

// ---------------- CSR gather + self-loop + BN statistics (fused) ----------------
__global__ void k_gather_stats(const float* __restrict__ H, float* __restrict__ AGG,
                               int N, int C) {
    int c = threadIdx.x;
    float s = 0.f, sq = 0.f;
    for (int i = blockIdx.x; i < N; i += gridDim.x) {
        int st = g_rowStart[i];
        int en = g_rowStart[i + 1];
        float acc = g_selfn[i] * H[(size_t)i * C + c];
        for (int j = st; j < en; j++) {
            int sn = g_csr_src[j];
            acc += g_csr_w[j] * H[(size_t)sn * C + c];
        }
        AGG[(size_t)i * C + c] = acc;
        s  += acc;
        sq += acc * acc;
    }
    atomicAdd(&g_stats[c], s);
    atomicAdd(&g_stats[C + c], sq);
}

__global__ void k_finalize_stats(const float* __restrict__ gamma,
                                 const float* __restrict__ beta, int N, int C) {
    int c = threadIdx.x;
    if (c < C) {
        float invN = 1.0f / (float)N;
        float mean = g_stats[c] * invN;
        float var  = g_stats[C + c] * invN - mean * mean;
        float sc   = gamma[c] * rsqrtf(var + 1e-5f);
        g_scale[c] = sc;
        g_shift[c] = beta[c] - mean * sc;
    }
}

// ---------------- pool with fused BN+ReLU (batch sorted) ----------------
__global__ void k_pool(const float* __restrict__ AGG, const int* __restrict__ batch,
                       int N, int G) {
    int g = blockIdx.x;
    int c = threadIdx.x;
    __shared__ int s_lo, s_hi;
    if (c == 0) {
        int lo = 0, hi = N;
        while (lo < hi) { int m = (lo + hi) >> 1; if (batch[m] < g) lo = m + 1; else hi = m; }
        s_lo = lo;
        int lo2 = lo, hi2 = N;
        while (lo2 < hi2) { int m = (lo2 + hi2) >> 1; if (batch[m] <= g) lo2 = m + 1; else hi2 = m; }
        s_hi = lo2;
    }
    __syncthreads();
    float sc = g_scale[c], sh = g_shift[c];
    float sum = 0.f;
    for (int i = s_lo; i < s_hi; i++)
        sum += fmaxf(0.f, AGG[(size_t)i * 256 + c] * sc + sh);
    int cnt = s_hi - s_lo;
    g_pooled[(size_t)g * 256 + c] = sum / fmaxf((float)cnt, 1.0f);
}

// ---------------- host launcher ----------------
extern "C" void kernel_launch(void* const* d_in, const int* in_sizes, int n_in,
                              void* d_out, int out_size) {
    const float* x     = (const float*)d_in[0];
    const int*   ei    = (const int*)d_in[1];
    const int*   batch = (const int*)d_in[2];
    const float* W1  = (const float*)d_in[4];
    const float* g1  = (const float*)d_in[6];
    const float* be1 = (const float*)d_in[7];
    const float* W2  = (const float*)d_in[8];
    const float* g2  = (const float*)d_in[10];
    const float* be2 = (const float*)d_in[11];
    const float* W3  = (const float*)d_in[12];
    const float* g3  = (const float*)d_in[14];
    const float* be3 = (const float*)d_in[15];
    const float* Wp  = (const float*)d_in[16];
    const float* bp  = (const float*)d_in[17];
    float* out = (float*)d_out;

    const int N = in_sizes[0] / 9;
    const int E = in_sizes[1] / 2;
    const int G = out_size / 256;
    const int NB = (N + 255) / 256;

    void *pA, *pB, *pPooled, *pStats, *pDegi, *pFill, *pScale, *pShift;
    void *pWt2, *pWt3, *pWtp;
    cudaGetSymbolAddress(&pA, g_bufA);
    cudaGetSymbolAddress(&pB, g_bufB);
    cudaGetSymbolAddress(&pPooled, g_pooled);
    cudaGetSymbolAddress(&pStats, g_stats);
    cudaGetSymbolAddress(&pDegi, g_degi);
    cudaGetSymbolAddress(&pFill, g_fill);
    cudaGetSymbolAddress(&pScale, g_scale);
    cudaGetSymbolAddress(&pShift, g_shift);
    cudaGetSymbolAddress(&pWt2, g_Wt2);
    cudaGetSymbolAddress(&pWt3, g_Wt3);
    cudaGetSymbolAddress(&pWtp, g_Wtp);
    float* bufA = (float*)pA;
    float* bufB = (float*)pB;
    const float* dScale = (const float*)pScale;
    const float* dShift = (const float*)pShift;

    const int* src = ei;
    const int* dst = ei + E;

    // ---- prep: degree, CSR, weight transposes ----
    cudaMemsetAsync(pDegi, 0, N * sizeof(int), 0);
    cudaMemsetAsync(pFill, 0, N * sizeof(int), 0);
    k_deg_accum<<<(E + 255) / 256, 256>>>(dst, E);
    k_dis_self<<<(N + 255) / 256, 256>>>(N);
    k_scan1<<<NB, 256>>>(N);
    k_scan2<<<1, SCAN_NB>>>(NB);
    k_scan3<<<NB, 256>>>(N, E);
    k_csr_fill<<<(E + 255) / 256, 256>>>(src, dst, E);
    k_transpose<<<(128 * 256 + 255) / 256, 256>>>(W2, (float*)pWt2, 128, 256);
    k_transpose<<<(256 * 256 + 255) / 256, 256>>>(W3, (float*)pWt3, 256, 256);
    k_transpose<<<(256 * 256 + 255) / 256, 256>>>(Wp, (float*)pWtp, 256, 256);

    // ---- Layer 1: [N,9] -> [N,128] ----
    k_gemm_k9<<<(N * 128 + 255) / 256, 256>>>(x, W1, bufB, N);
    cudaMemsetAsync(pStats, 0, 2 * 128 * sizeof(float), 0);
    k_gather_stats<<<2048, 128>>>(bufB, bufA, N, 128);
    k_finalize_stats<<<1, 128>>>(g1, be1, N, 128);

    // ---- Layer 2: bn_relu(agg1) @ W2 -> [N,256] (tf32 mma) ----
    {
        dim3 grid(2, (N + 127) / 128);
        k_mma<<<grid, 256>>>(bufA, (const float*)pWt2, bufB, N, 128, 256,
                             nullptr, dScale, dShift);
        cudaMemsetAsync(pStats, 0, 2 * 256 * sizeof(float), 0);
        k_gather_stats<<<2048, 256>>>(bufB, bufA, N, 256);
        k_finalize_stats<<<1, 256>>>(g2, be2, N, 256);
    }

    // ---- Layer 3: bn_relu(agg2) @ W3 -> [N,256] (tf32 mma) ----
    {
        dim3 grid(2, (N + 127) / 128);
        k_mma<<<grid, 256>>>(bufA, (const float*)pWt3, bufB, N, 256, 256,
                             nullptr, dScale, dShift);
        cudaMemsetAsync(pStats, 0, 2 * 256 * sizeof(float), 0);
        k_gather_stats<<<2048, 256>>>(bufB, bufA, N, 256);
        k_finalize_stats<<<1, 256>>>(g3, be3, N, 256);
    }

    // ---- pool (fused BN3+ReLU) + final linear (tf32 mma) ----
    k_pool<<<G, 256>>>(bufA, batch, N, G);
    {
        dim3 grid(2, (G + 127) / 128);
        k_mma<<<grid, 256>>>((const float*)pPooled, (const float*)pWtp, out, G, 256, 256,
                             bp, nullptr, nullptr);
    }
}

// round 6
// speedup vs baseline: 4.0880x; 1.4735x over previous
#include <cuda_runtime.h>
#include <math.h>
#include <stdint.h>

#define NMAXN 200000
#define EMAXE 400000
#define GMAXG 8192
#define CMAX  256
#define SCAN_NB 1024

// ---------------- scratch (static device globals; no allocation) ----------------
__device__ float g_bufA[(size_t)NMAXN * CMAX];   // aggregated (GEMM input)
__device__ float g_bufB[(size_t)NMAXN * CMAX];   // GEMM output Y
__device__ float g_agg9[(size_t)NMAXN * 12];     // layer-1 aggregated x (padded to 12)
__device__ float g_dis[NMAXN];
__device__ float g_selfn[NMAXN];
__device__ int   g_degi[NMAXN];
__device__ int   g_rowStart[NMAXN + 1];
__device__ int   g_blkSum[SCAN_NB];
__device__ int   g_fill[NMAXN];
__device__ int   g_csr_src[EMAXE];
__device__ float g_csr_w[EMAXE];
__device__ float g_pooled[(size_t)GMAXG * CMAX];
__device__ float g_stats[2 * CMAX];              // sum at [c], sumsq at [256+c]
__device__ float g_scale[CMAX];
__device__ float g_shift[CMAX];
__device__ float g_Wt2[128 * 256];
__device__ float g_Wt3[256 * 256];
__device__ float g_Wtp[256 * 256];

// ---------------- helpers ----------------
__device__ __forceinline__ uint32_t smem_u32(const void* p) {
    uint32_t a;
    asm("{ .reg .u64 t; cvta.to.shared.u64 t, %1; cvt.u32.u64 %0, t; }" : "=r"(a) : "l"(p));
    return a;
}
__device__ __forceinline__ float tf32r(float x) {
    uint32_t u;
    asm("cvt.rna.tf32.f32 %0, %1;" : "=r"(u) : "f"(x));
    return __uint_as_float(u);
}
__device__ __forceinline__ void mma_tf32(float d[4], const uint32_t a[4], const uint32_t b[2]) {
    asm volatile(
        "mma.sync.aligned.m16n8k8.row.col.f32.tf32.tf32.f32 "
        "{%0,%1,%2,%3}, {%4,%5,%6,%7}, {%8,%9}, {%0,%1,%2,%3};"
        : "+f"(d[0]), "+f"(d[1]), "+f"(d[2]), "+f"(d[3])
        : "r"(a[0]), "r"(a[1]), "r"(a[2]), "r"(a[3]), "r"(b[0]), "r"(b[1]));
}
__device__ __forceinline__ void cp_async8(uint32_t daddr, const void* gptr, uint32_t srcsz) {
    asm volatile("cp.async.ca.shared.global [%0], [%1], 8, %2;"
                 :: "r"(daddr), "l"(gptr), "r"(srcsz) : "memory");
}
#define CP_COMMIT() asm volatile("cp.async.commit_group;" ::: "memory")
#define CP_WAIT1()  asm volatile("cp.async.wait_group 1;" ::: "memory")

// ---------------- prep ----------------
__global__ void k_zero(int N) {
    int i = blockIdx.x * blockDim.x + threadIdx.x;
    if (i < N) { g_degi[i] = 0; g_fill[i] = 0; }
    if (i < 2 * CMAX) g_stats[i] = 0.f;
}
__global__ void k_deg_accum(const int* __restrict__ dst, int E) {
    int e = blockIdx.x * blockDim.x + threadIdx.x;
    if (e < E) atomicAdd(&g_degi[dst[e]], 1);
}
__global__ void k_dis_self(int N) {
    int i = blockIdx.x * blockDim.x + threadIdx.x;
    if (i < N) {
        float d = (float)(g_degi[i] + 1);
        g_dis[i] = rsqrtf(d);
        g_selfn[i] = 1.0f / d;
    }
}
__global__ void k_scan1(int N) {
    __shared__ int sh[256];
    int i = blockIdx.x * 256 + threadIdx.x;
    int v = (i < N) ? g_degi[i] : 0;
    sh[threadIdx.x] = v;
    __syncthreads();
    for (int off = 1; off < 256; off <<= 1) {
        int t = (threadIdx.x >= off) ? sh[threadIdx.x - off] : 0;
        __syncthreads();
        sh[threadIdx.x] += t;
        __syncthreads();
    }
    if (i < N) g_rowStart[i] = sh[threadIdx.x] - v;
    if (threadIdx.x == 255) g_blkSum[blockIdx.x] = sh[255];
}
__global__ void k_scan2(int NB) {
    __shared__ int sh[SCAN_NB];
    int v = ((int)threadIdx.x < NB) ? g_blkSum[threadIdx.x] : 0;
    sh[threadIdx.x] = v;
    __syncthreads();
    for (int off = 1; off < SCAN_NB; off <<= 1) {
        int t = ((int)threadIdx.x >= off) ? sh[threadIdx.x - off] : 0;
        __syncthreads();
        sh[threadIdx.x] += t;
        __syncthreads();
    }
    if ((int)threadIdx.x < NB) g_blkSum[threadIdx.x] = sh[threadIdx.x] - v;
}
__global__ void k_scan3(int N, int E) {
    int i = blockIdx.x * blockDim.x + threadIdx.x;
    if (i < N) g_rowStart[i] += g_blkSum[i >> 8];
    if (i == 0) g_rowStart[N] = E;
}
__global__ void k_csr_fill(const int* __restrict__ src, const int* __restrict__ dst, int E) {
    int e = blockIdx.x * blockDim.x + threadIdx.x;
    if (e < E) {
        int s = src[e], d = dst[e];
        int pos = g_rowStart[d] + atomicAdd(&g_fill[d], 1);
        g_csr_src[pos] = s;
        g_csr_w[pos]   = g_dis[s] * g_dis[d];
    }
}
__global__ void k_transpose(const float* __restrict__ W, float* __restrict__ Wt,
                            int K, int N) {
    int idx = blockIdx.x * blockDim.x + threadIdx.x;
    if (idx < K * N) {
        int k = idx / N, n = idx % N;
        Wt[(size_t)n * K + k] = tf32r(W[idx]);
    }
}

// ---------------- layer-1 gather: P1 = A * x  (9 channels) ----------------
__global__ void k_gather9(const float* __restrict__ x, int N) {
    int i = blockIdx.x * blockDim.x + threadIdx.x;
    if (i >= N) return;
    float acc[9];
    float w0 = g_selfn[i];
    const float* xr = x + (size_t)i * 9;
#pragma unroll
    for (int k = 0; k < 9; k++) acc[k] = w0 * xr[k];
    int st = g_rowStart[i], en = g_rowStart[i + 1];
    for (int j = st; j < en; j++) {
        int s = g_csr_src[j];
        float w = g_csr_w[j];
        const float* xs = x + (size_t)s * 9;
#pragma unroll
        for (int k = 0; k < 9; k++) acc[k] += w * xs[k];
    }
    float* o = g_agg9 + (size_t)i * 12;
#pragma unroll
    for (int k = 0; k < 9; k++) o[k] = acc[k];
}

// ---------------- layer-1 GEMM + fused stats: Y1 = P1 @ W1, [N,9]x[9,128] ----------------
__global__ __launch_bounds__(128) void k_gemm9s(const float* __restrict__ W,
                                                float* __restrict__ Y, int N) {
    __shared__ float Ws[9 * 128];
    __shared__ float xs[64 * 12];
    int c = threadIdx.x;
    for (int i = c; i < 9 * 128; i += 128) Ws[i] = W[i];
    int row0 = blockIdx.x * 64;
    for (int i = c; i < 64 * 12 / 4; i += 128) {
        int gidx = row0 * 12 + i * 4;
        float4 v = (gidx < N * 12) ? *(const float4*)(g_agg9 + gidx)
                                   : make_float4(0.f, 0.f, 0.f, 0.f);
        *(float4*)(xs + i * 4) = v;
    }
    __syncthreads();
    float wcol[9];
#pragma unroll
    for (int k = 0; k < 9; k++) wcol[k] = Ws[k * 128 + c];
    float s = 0.f, sq = 0.f;
    int rmax = min(64, N - row0);
    for (int r = 0; r < rmax; r++) {
        float acc = 0.f;
#pragma unroll
        for (int k = 0; k < 9; k++) acc += xs[r * 12 + k] * wcol[k];
        Y[(size_t)(row0 + r) * 128 + c] = acc;
        s += acc;
        sq += acc * acc;
    }
    atomicAdd(&g_stats[c], s);
    atomicAdd(&g_stats[256 + c], sq);
}

// ---------------- BN finalize (also resets stats for next layer) ----------------
__global__ void k_finalize(const float* __restrict__ gamma,
                           const float* __restrict__ beta, int N, int C) {
    int c = threadIdx.x;
    if (c < C) {
        float invN = 1.0f / (float)N;
        float mean = g_stats[c] * invN;
        float var  = g_stats[256 + c] * invN - mean * mean;
        float sc   = gamma[c] * rsqrtf(var + 1e-5f);
        g_scale[c] = sc;
        g_shift[c] = beta[c] - mean * sc;
        g_stats[c] = 0.f;
        g_stats[256 + c] = 0.f;
    }
}

// ---------------- gather with fused BN+ReLU: P = A * bnrelu(Y), tf32-rounded out ----------------
__global__ void k_gather_bn(const float* __restrict__ Y, float* __restrict__ P,
                            int N, int C) {
    int c = threadIdx.x;
    float sc = g_scale[c], sh = g_shift[c];
    for (int i = blockIdx.x; i < N; i += gridDim.x) {
        float acc = g_selfn[i] * fmaxf(0.f, Y[(size_t)i * C + c] * sc + sh);
        int st = g_rowStart[i], en = g_rowStart[i + 1];
        for (int j = st; j < en; j++) {
            int s = g_csr_src[j];
            acc += g_csr_w[j] * fmaxf(0.f, Y[(size_t)s * C + c] * sc + sh);
        }
        P[(size_t)i * C + c] = tf32r(acc);
    }
}

// ---------------- tf32 mma GEMM, cp.async double-buffered, fused stats ----------------
// C[M,256] = A[M,K] @ Wt^T (Wt [256,K] row-major, tf32 pre-rounded).
// If doStats: per-column sum/sumsq atomically added to g_stats.
__global__ __launch_bounds__(256, 2) void k_mma(const float* __restrict__ A,
                                                const float* __restrict__ Wt,
                                                float* __restrict__ C,
                                                int M, int K,
                                                const float* __restrict__ bias,
                                                int doStats) {
    extern __shared__ __align__(16) float sm[];   // [2][128][36] A + [2][128][36] B
    const int tid  = threadIdx.x;
    const int wid  = tid >> 5;
    const int lane = tid & 31;
    const int wr   = (wid & 1) * 64;
    const int wc   = (wid >> 1) * 32;
    const int row0 = blockIdx.y * 128;
    const int col0 = blockIdx.x * 128;
    const int gq   = lane >> 2;
    const int tq   = lane & 3;
    const uint32_t sbase = smem_u32(sm);
    const int nk = K >> 5;

    float acc[4][4][4];
#pragma unroll
    for (int mt = 0; mt < 4; mt++)
#pragma unroll
        for (int nt = 0; nt < 4; nt++)
#pragma unroll
            for (int q = 0; q < 4; q++) acc[mt][nt][q] = 0.f;

    // stage loader: 8-byte cp.async, 16 chunks per 32-float row
    auto load_stage = [&](int s, int k0) {
#pragma unroll
        for (int i = 0; i < 8; i++) {
            int idx = tid + i * 256;            // 0..2047
            int r = idx >> 4, j2 = idx & 15;    // row, 8B-chunk
            int gr = row0 + r;
            uint32_t da = sbase + (uint32_t)(s * 4608 + r * 36 + j2 * 2) * 4;
            cp_async8(da, A + (size_t)gr * K + k0 + j2 * 2, (gr < M) ? 8u : 0u);
        }
#pragma unroll
        for (int i = 0; i < 8; i++) {
            int idx = tid + i * 256;
            int n = idx >> 4, j2 = idx & 15;
            uint32_t db = sbase + (uint32_t)(9216 + s * 4608 + n * 36 + j2 * 2) * 4;
            cp_async8(db, Wt + (size_t)(col0 + n) * K + k0 + j2 * 2, 8u);
        }
    };

    load_stage(0, 0);
    CP_COMMIT();
    for (int kt = 0; kt < nk; kt++) {
        if (kt + 1 < nk) load_stage((kt + 1) & 1, (kt + 1) * 32);
        CP_COMMIT();
        CP_WAIT1();
        __syncthreads();
        const float* As = sm + (kt & 1) * 4608;
        const float* Bs = sm + 9216 + (kt & 1) * 4608;
#pragma unroll
        for (int kk = 0; kk < 4; kk++) {
            uint32_t af[4][4], bf[4][2];
#pragma unroll
            for (int mt = 0; mt < 4; mt++) {
                int r = wr + mt * 16 + gq;
                af[mt][0] = __float_as_uint(As[r * 36 + kk * 8 + tq]);
                af[mt][1] = __float_as_uint(As[(r + 8) * 36 + kk * 8 + tq]);
                af[mt][2] = __float_as_uint(As[r * 36 + kk * 8 + 4 + tq]);
                af[mt][3] = __float_as_uint(As[(r + 8) * 36 + kk * 8 + 4 + tq]);
            }
#pragma unroll
            for (int nt = 0; nt < 4; nt++) {
                int n = wc + nt * 8 + gq;
                bf[nt][0] = __float_as_uint(Bs[n * 36 + kk * 8 + tq]);
                bf[nt][1] = __float_as_uint(Bs[n * 36 + kk * 8 + 4 + tq]);
            }
#pragma unroll
            for (int mt = 0; mt < 4; mt++)
#pragma unroll
                for (int nt = 0; nt < 4; nt++)
                    mma_tf32(acc[mt][nt], af[mt], bf[nt]);
        }
        __syncthreads();
    }

    // ---- write C (+bias) ----
#pragma unroll
    for (int mt = 0; mt < 4; mt++) {
        int r0 = row0 + wr + mt * 16 + gq;
        int r1 = r0 + 8;
#pragma unroll
        for (int nt = 0; nt < 4; nt++) {
            int c = col0 + wc + nt * 8 + tq * 2;
            float b0 = 0.f, b1 = 0.f;
            if (bias) { b0 = bias[c]; b1 = bias[c + 1]; }
            if (r0 < M)
                *(float2*)(C + (size_t)r0 * 256 + c) =
                    make_float2(acc[mt][nt][0] + b0, acc[mt][nt][1] + b1);
            if (r1 < M)
                *(float2*)(C + (size_t)r1 * 256 + c) =
                    make_float2(acc[mt][nt][2] + b0, acc[mt][nt][3] + b1);
        }
    }

    // ---- fused per-column stats (OOB rows contribute exact zeros) ----
    if (doStats) {
#pragma unroll
        for (int nt = 0; nt < 4; nt++) {
#pragma unroll
            for (int q = 0; q < 2; q++) {
                float s = 0.f, sq = 0.f;
#pragma unroll
                for (int mt = 0; mt < 4; mt++) {
                    float a = acc[mt][nt][q], b = acc[mt][nt][q + 2];
                    s += a + b;
                    sq += a * a + b * b;
                }
#pragma unroll
                for (int off = 4; off < 32; off <<= 1) {
                    s  += __shfl_xor_sync(0xFFFFFFFF, s, off);
                    sq += __shfl_xor_sync(0xFFFFFFFF, sq, off);
                }
                if (gq == 0) {
                    int c = col0 + wc + nt * 8 + tq * 2 + q;
                    atomicAdd(&g_stats[c], s);
                    atomicAdd(&g_stats[256 + c], sq);
                }
            }
        }
    }
}

// ---------------- pool with fused BN+ReLU (batch sorted), tf32-rounded out ----------------
__global__ void k_pool(const float* __restrict__ Y, const int* __restrict__ batch,
                       int N, int G) {
    int g = blockIdx.x;
    int c = threadIdx.x;
    __shared__ int s_lo, s_hi;
    if (c == 0) {
        int lo = 0, hi = N;
        while (lo < hi) { int m = (lo + hi) >> 1; if (batch[m] < g) lo = m + 1; else hi = m; }
        s_lo = lo;
        int lo2 = lo, hi2 = N;
        while (lo2 < hi2) { int m = (lo2 + hi2) >> 1; if (batch[m] <= g) lo2 = m + 1; else hi2 = m; }
        s_hi = lo2;
    }
    __syncthreads();
    float sc = g_scale[c], sh = g_shift[c];
    float sum = 0.f;
    for (int i = s_lo; i < s_hi; i++)
        sum += fmaxf(0.f, Y[(size_t)i * 256 + c] * sc + sh);
    int cnt = s_hi - s_lo;
    g_pooled[(size_t)g * 256 + c] = tf32r(sum / fmaxf((float)cnt, 1.0f));
}

// ---------------- host launcher ----------------
extern "C" void kernel_launch(void* const* d_in, const int* in_sizes, int n_in,
                              void* d_out, int out_size) {
    const float* x     = (const float*)d_in[0];
    const int*   ei    = (const int*)d_in[1];
    const int*   batch = (const int*)d_in[2];
    const float* W1  = (const float*)d_in[4];
    const float* g1  = (const float*)d_in[6];
    const float* be1 = (const float*)d_in[7];
    const float* W2  = (const float*)d_in[8];
    const float* g2  = (const float*)d_in[10];
    const float* be2 = (const float*)d_in[11];
    const float* W3  = (const float*)d_in[12];
    const float* g3  = (const float*)d_in[14];
    const float* be3 = (const float*)d_in[15];
    const float* Wp  = (const float*)d_in[16];
    const float* bp  = (const float*)d_in[17];
    float* out = (float*)d_out;

    const int N = in_sizes[0] / 9;
    const int E = in_sizes[1] / 2;
    const int G = out_size / 256;
    const int NB = (N + 255) / 256;
    const int SMEM_MMA = 4 * 4608 * 4;  // 73728 bytes

    cudaFuncSetAttribute(k_mma, cudaFuncAttributeMaxDynamicSharedMemorySize, SMEM_MMA);

    void *pA, *pB, *pPooled, *pWt2, *pWt3, *pWtp;
    cudaGetSymbolAddress(&pA, g_bufA);
    cudaGetSymbolAddress(&pB, g_bufB);
    cudaGetSymbolAddress(&pPooled, g_pooled);
    cudaGetSymbolAddress(&pWt2, g_Wt2);
    cudaGetSymbolAddress(&pWt3, g_Wt3);
    cudaGetSymbolAddress(&pWtp, g_Wtp);
    float* bufA = (float*)pA;
    float* bufB = (float*)pB;

    const int* src = ei;
    const int* dst = ei + E;

    // ---- prep ----
    k_zero<<<NB, 256>>>(N);
    k_deg_accum<<<(E + 255) / 256, 256>>>(dst, E);
    k_dis_self<<<(N + 255) / 256, 256>>>(N);
    k_scan1<<<NB, 256>>>(N);
    k_scan2<<<1, SCAN_NB>>>(NB);
    k_scan3<<<NB, 256>>>(N, E);
    k_csr_fill<<<(E + 255) / 256, 256>>>(src, dst, E);
    k_transpose<<<(128 * 256 + 255) / 256, 256>>>(W2, (float*)pWt2, 128, 256);
    k_transpose<<<(256 * 256 + 255) / 256, 256>>>(W3, (float*)pWt3, 256, 256);
    k_transpose<<<(256 * 256 + 255) / 256, 256>>>(Wp, (float*)pWtp, 256, 256);

    // ---- Layer 1: P1 = A*x (9ch); Y1 = P1@W1 (+stats); finalize ----
    k_gather9<<<(N + 255) / 256, 256>>>(x, N);
    k_gemm9s<<<(N + 63) / 64, 128>>>(W1, bufB, N);
    k_finalize<<<1, 128>>>(g1, be1, N, 128);

    // ---- Layer 2: P2 = A*bnrelu(Y1) (128ch); Y2 = P2@W2 (+stats); finalize ----
    k_gather_bn<<<2048, 128>>>(bufB, bufA, N, 128);
    {
        dim3 grid(2, (N + 127) / 128);
        k_mma<<<grid, 256, SMEM_MMA>>>(bufA, (const float*)pWt2, bufB, N, 128, nullptr, 1);
    }
    k_finalize<<<1, 256>>>(g2, be2, N, 256);

    // ---- Layer 3: P3 = A*bnrelu(Y2) (256ch); Y3 = P3@W3 (+stats); finalize ----
    k_gather_bn<<<2048, 256>>>(bufB, bufA, N, 256);
    {
        dim3 grid(2, (N + 127) / 128);
        k_mma<<<grid, 256, SMEM_MMA>>>(bufA, (const float*)pWt3, bufB, N, 256, nullptr, 1);
    }
    k_finalize<<<1, 256>>>(g3, be3, N, 256);

    // ---- pool (fused BN3+ReLU) + final linear ----
    k_pool<<<G, 256>>>(bufB, batch, N, G);
    {
        dim3 grid(2, (G + 127) / 128);
        k_mma<<<grid, 256, SMEM_MMA>>>((const float*)pPooled, (const float*)pWtp, out,
                                       G, 256, bp, 0);
    }
}

// round 7
// speedup vs baseline: 4.7129x; 1.1529x over previous
#include <cuda_runtime.h>
#include <math.h>
#include <stdint.h>

#define NMAXN 200000
#define EMAXE 400000
#define GMAXG 8192
#define CMAX  256
#define SCAN_NB 1024

// ---------------- scratch (static device globals; no allocation) ----------------
__device__ float g_bufA[(size_t)NMAXN * CMAX];   // aggregated (GEMM input)
__device__ float g_bufB[(size_t)NMAXN * CMAX];   // GEMM output Y
__device__ float g_dis[NMAXN];
__device__ float g_selfn[NMAXN];
__device__ int   g_degi[NMAXN];
__device__ int   g_rowStart[NMAXN + 1];
__device__ int   g_blkSum[SCAN_NB];
__device__ int   g_fill[NMAXN];
__device__ int   g_csr_src[EMAXE];
__device__ float g_csr_w[EMAXE];
__device__ float g_pooled[(size_t)GMAXG * CMAX];
__device__ float g_stats[2 * CMAX];              // sum at [c], sumsq at [256+c]
__device__ float g_scale[CMAX];
__device__ float g_shift[CMAX];
__device__ float g_Wt2[128 * 256];
__device__ float g_Wt3[256 * 256];
__device__ float g_Wtp[256 * 256];

// ---------------- helpers ----------------
__device__ __forceinline__ uint32_t smem_u32(const void* p) {
    uint32_t a;
    asm("{ .reg .u64 t; cvta.to.shared.u64 t, %1; cvt.u32.u64 %0, t; }" : "=r"(a) : "l"(p));
    return a;
}
__device__ __forceinline__ float tf32r(float x) {
    uint32_t u;
    asm("cvt.rna.tf32.f32 %0, %1;" : "=r"(u) : "f"(x));
    return __uint_as_float(u);
}
__device__ __forceinline__ void mma_tf32(float d[4], const uint32_t a[4], const uint32_t b[2]) {
    asm volatile(
        "mma.sync.aligned.m16n8k8.row.col.f32.tf32.tf32.f32 "
        "{%0,%1,%2,%3}, {%4,%5,%6,%7}, {%8,%9}, {%0,%1,%2,%3};"
        : "+f"(d[0]), "+f"(d[1]), "+f"(d[2]), "+f"(d[3])
        : "r"(a[0]), "r"(a[1]), "r"(a[2]), "r"(a[3]), "r"(b[0]), "r"(b[1]));
}
__device__ __forceinline__ void cp_async8(uint32_t daddr, const void* gptr, uint32_t srcsz) {
    asm volatile("cp.async.ca.shared.global [%0], [%1], 8, %2;"
                 :: "r"(daddr), "l"(gptr), "r"(srcsz) : "memory");
}
#define CP_COMMIT() asm volatile("cp.async.commit_group;" ::: "memory")
#define CP_WAIT1()  asm volatile("cp.async.wait_group 1;" ::: "memory")

// ---------------- prep: zero counters + tf32-transpose all weights ----------------
__global__ void k_zero_trans(const float* __restrict__ W2, const float* __restrict__ W3,
                             const float* __restrict__ Wp, int N) {
    int i = blockIdx.x * blockDim.x + threadIdx.x;
    if (i < N) { g_degi[i] = 0; g_fill[i] = 0; }
    if (i < 2 * CMAX) g_stats[i] = 0.f;
    if (i < 128 * 256) {
        int k = i / 256, n = i % 256;
        g_Wt2[(size_t)n * 128 + k] = tf32r(W2[i]);
    }
    if (i < 256 * 256) {
        int k = i / 256, n = i % 256;
        g_Wt3[(size_t)n * 256 + k] = tf32r(W3[i]);
        g_Wtp[(size_t)n * 256 + k] = tf32r(Wp[i]);
    }
}
__global__ void k_deg_accum(const int* __restrict__ dst, int E) {
    int e = blockIdx.x * blockDim.x + threadIdx.x;
    if (e < E) atomicAdd(&g_degi[dst[e]], 1);
}
__global__ void k_dis_self(int N) {
    int i = blockIdx.x * blockDim.x + threadIdx.x;
    if (i < N) {
        float d = (float)(g_degi[i] + 1);
        g_dis[i] = rsqrtf(d);
        g_selfn[i] = 1.0f / d;
    }
}
__global__ void k_scan1(int N) {
    __shared__ int sh[256];
    int i = blockIdx.x * 256 + threadIdx.x;
    int v = (i < N) ? g_degi[i] : 0;
    sh[threadIdx.x] = v;
    __syncthreads();
    for (int off = 1; off < 256; off <<= 1) {
        int t = (threadIdx.x >= off) ? sh[threadIdx.x - off] : 0;
        __syncthreads();
        sh[threadIdx.x] += t;
        __syncthreads();
    }
    if (i < N) g_rowStart[i] = sh[threadIdx.x] - v;
    if (threadIdx.x == 255) g_blkSum[blockIdx.x] = sh[255];
}
__global__ void k_scan2(int NB) {
    __shared__ int sh[SCAN_NB];
    int v = ((int)threadIdx.x < NB) ? g_blkSum[threadIdx.x] : 0;
    sh[threadIdx.x] = v;
    __syncthreads();
    for (int off = 1; off < SCAN_NB; off <<= 1) {
        int t = ((int)threadIdx.x >= off) ? sh[threadIdx.x - off] : 0;
        __syncthreads();
        sh[threadIdx.x] += t;
        __syncthreads();
    }
    if ((int)threadIdx.x < NB) g_blkSum[threadIdx.x] = sh[threadIdx.x] - v;
}
__global__ void k_scan3(int N, int E) {
    int i = blockIdx.x * blockDim.x + threadIdx.x;
    if (i < N) g_rowStart[i] += g_blkSum[i >> 8];
    if (i == 0) g_rowStart[N] = E;
}
__global__ void k_csr_fill(const int* __restrict__ src, const int* __restrict__ dst, int E) {
    int e = blockIdx.x * blockDim.x + threadIdx.x;
    if (e < E) {
        int s = src[e], d = dst[e];
        int pos = g_rowStart[d] + atomicAdd(&g_fill[d], 1);
        g_csr_src[pos] = s;
        g_csr_w[pos]   = g_dis[s] * g_dis[d];
    }
}

// ---------------- fused layer-1: gather9 + GEMM[9->128] + stats ----------------
// warp per node; lanes 0-8 gather channels, shfl-broadcast, all lanes emit 4 outputs
__global__ __launch_bounds__(256) void k_layer1(const float* __restrict__ x,
                                                const float* __restrict__ W1,
                                                float* __restrict__ Y, int N) {
    __shared__ float Ws[9 * 128];
    __shared__ float sstat[256];   // [0:128) sum, [128:256) sumsq
    int tid = threadIdx.x;
    for (int i = tid; i < 9 * 128; i += 256) Ws[i] = W1[i];
    sstat[tid] = 0.f;
    __syncthreads();
    int wid = tid >> 5, lane = tid & 31;
    int i = blockIdx.x * 8 + wid;
    if (i < N) {
        float acc = 0.f;
        if (lane < 9) acc = g_selfn[i] * x[(size_t)i * 9 + lane];
        int st = g_rowStart[i], en = g_rowStart[i + 1];
        for (int j = st; j < en; j++) {
            int s = g_csr_src[j];
            float w = g_csr_w[j];
            if (lane < 9) acc += w * x[(size_t)s * 9 + lane];
        }
        float a[9];
#pragma unroll
        for (int k = 0; k < 9; k++) a[k] = __shfl_sync(0xFFFFFFFF, acc, k);
#pragma unroll
        for (int q = 0; q < 4; q++) {
            int c = q * 32 + lane;
            float y = 0.f;
#pragma unroll
            for (int k = 0; k < 9; k++) y += a[k] * Ws[k * 128 + c];
            Y[(size_t)i * 128 + c] = y;
            atomicAdd(&sstat[c], y);
            atomicAdd(&sstat[128 + c], y * y);
        }
    }
    __syncthreads();
    if (tid < 128) {
        atomicAdd(&g_stats[tid], sstat[tid]);
        atomicAdd(&g_stats[256 + tid], sstat[128 + tid]);
    }
}

// ---------------- BN finalize (also resets stats for next layer) ----------------
__global__ void k_finalize(const float* __restrict__ gamma,
                           const float* __restrict__ beta, int N, int C) {
    int c = threadIdx.x;
    if (c < C) {
        float invN = 1.0f / (float)N;
        float mean = g_stats[c] * invN;
        float var  = g_stats[256 + c] * invN - mean * mean;
        float sc   = gamma[c] * rsqrtf(var + 1e-5f);
        g_scale[c] = sc;
        g_shift[c] = beta[c] - mean * sc;
        g_stats[c] = 0.f;
        g_stats[256 + c] = 0.f;
    }
}

// ---------------- gather + fused BN+ReLU, multi-node blocks, float4 ----------------
// C channels; TPN = C/4 threads per node; NPB = 256/TPN nodes per block.
template <int C>
__global__ __launch_bounds__(256) void k_gather_bn4(const float* __restrict__ Y,
                                                    float* __restrict__ P, int N) {
    constexpr int TPN = C / 4;
    constexpr int NPB = 256 / TPN;
    const int sub = threadIdx.x / TPN;
    const int cq  = threadIdx.x % TPN;
    const int i   = blockIdx.x * NPB + sub;
    if (i >= N) return;
    const float4 sc = ((const float4*)g_scale)[cq];
    const float4 sh = ((const float4*)g_shift)[cq];
    const float4* Yv = (const float4*)Y;
    float w0 = g_selfn[i];
    float4 y = Yv[(size_t)i * TPN + cq];
    float4 acc;
    acc.x = w0 * fmaxf(0.f, y.x * sc.x + sh.x);
    acc.y = w0 * fmaxf(0.f, y.y * sc.y + sh.y);
    acc.z = w0 * fmaxf(0.f, y.z * sc.z + sh.z);
    acc.w = w0 * fmaxf(0.f, y.w * sc.w + sh.w);
    int st = g_rowStart[i], en = g_rowStart[i + 1];
    for (int j = st; j < en; j++) {
        int s = g_csr_src[j];
        float w = g_csr_w[j];
        float4 v = Yv[(size_t)s * TPN + cq];
        acc.x += w * fmaxf(0.f, v.x * sc.x + sh.x);
        acc.y += w * fmaxf(0.f, v.y * sc.y + sh.y);
        acc.z += w * fmaxf(0.f, v.z * sc.z + sh.z);
        acc.w += w * fmaxf(0.f, v.w * sc.w + sh.w);
    }
    ((float4*)P)[(size_t)i * TPN + cq] =
        make_float4(tf32r(acc.x), tf32r(acc.y), tf32r(acc.z), tf32r(acc.w));
}

// ---------------- tf32 mma GEMM, cp.async double-buffered, fused stats ----------------
__global__ __launch_bounds__(256, 2) void k_mma(const float* __restrict__ A,
                                                const float* __restrict__ Wt,
                                                float* __restrict__ C,
                                                int M, int K,
                                                const float* __restrict__ bias,
                                                int doStats) {
    extern __shared__ __align__(16) float sm[];
    const int tid  = threadIdx.x;
    const int wid  = tid >> 5;
    const int lane = tid & 31;
    const int wr   = (wid & 1) * 64;
    const int wc   = (wid >> 1) * 32;
    const int row0 = blockIdx.y * 128;
    const int col0 = blockIdx.x * 128;
    const int gq   = lane >> 2;
    const int tq   = lane & 3;
    const uint32_t sbase = smem_u32(sm);
    const int nk = K >> 5;

    float acc[4][4][4];
#pragma unroll
    for (int mt = 0; mt < 4; mt++)
#pragma unroll
        for (int nt = 0; nt < 4; nt++)
#pragma unroll
            for (int q = 0; q < 4; q++) acc[mt][nt][q] = 0.f;

    auto load_stage = [&](int s, int k0) {
#pragma unroll
        for (int i = 0; i < 8; i++) {
            int idx = tid + i * 256;
            int r = idx >> 4, j2 = idx & 15;
            int gr = row0 + r;
            uint32_t da = sbase + (uint32_t)(s * 4608 + r * 36 + j2 * 2) * 4;
            cp_async8(da, A + (size_t)gr * K + k0 + j2 * 2, (gr < M) ? 8u : 0u);
        }
#pragma unroll
        for (int i = 0; i < 8; i++) {
            int idx = tid + i * 256;
            int n = idx >> 4, j2 = idx & 15;
            uint32_t db = sbase + (uint32_t)(9216 + s * 4608 + n * 36 + j2 * 2) * 4;
            cp_async8(db, Wt + (size_t)(col0 + n) * K + k0 + j2 * 2, 8u);
        }
    };

    load_stage(0, 0);
    CP_COMMIT();
    for (int kt = 0; kt < nk; kt++) {
        if (kt + 1 < nk) load_stage((kt + 1) & 1, (kt + 1) * 32);
        CP_COMMIT();
        CP_WAIT1();
        __syncthreads();
        const float* As = sm + (kt & 1) * 4608;
        const float* Bs = sm + 9216 + (kt & 1) * 4608;
#pragma unroll
        for (int kk = 0; kk < 4; kk++) {
            uint32_t af[4][4], bf[4][2];
#pragma unroll
            for (int mt = 0; mt < 4; mt++) {
                int r = wr + mt * 16 + gq;
                af[mt][0] = __float_as_uint(As[r * 36 + kk * 8 + tq]);
                af[mt][1] = __float_as_uint(As[(r + 8) * 36 + kk * 8 + tq]);
                af[mt][2] = __float_as_uint(As[r * 36 + kk * 8 + 4 + tq]);
                af[mt][3] = __float_as_uint(As[(r + 8) * 36 + kk * 8 + 4 + tq]);
            }
#pragma unroll
            for (int nt = 0; nt < 4; nt++) {
                int n = wc + nt * 8 + gq;
                bf[nt][0] = __float_as_uint(Bs[n * 36 + kk * 8 + tq]);
                bf[nt][1] = __float_as_uint(Bs[n * 36 + kk * 8 + 4 + tq]);
            }
#pragma unroll
            for (int mt = 0; mt < 4; mt++)
#pragma unroll
                for (int nt = 0; nt < 4; nt++)
                    mma_tf32(acc[mt][nt], af[mt], bf[nt]);
        }
        __syncthreads();
    }

#pragma unroll
    for (int mt = 0; mt < 4; mt++) {
        int r0 = row0 + wr + mt * 16 + gq;
        int r1 = r0 + 8;
#pragma unroll
        for (int nt = 0; nt < 4; nt++) {
            int c = col0 + wc + nt * 8 + tq * 2;
            float b0 = 0.f, b1 = 0.f;
            if (bias) { b0 = bias[c]; b1 = bias[c + 1]; }
            if (r0 < M)
                *(float2*)(C + (size_t)r0 * 256 + c) =
                    make_float2(acc[mt][nt][0] + b0, acc[mt][nt][1] + b1);
            if (r1 < M)
                *(float2*)(C + (size_t)r1 * 256 + c) =
                    make_float2(acc[mt][nt][2] + b0, acc[mt][nt][3] + b1);
        }
    }

    if (doStats) {
#pragma unroll
        for (int nt = 0; nt < 4; nt++) {
#pragma unroll
            for (int q = 0; q < 2; q++) {
                float s = 0.f, sq = 0.f;
#pragma unroll
                for (int mt = 0; mt < 4; mt++) {
                    float a = acc[mt][nt][q], b = acc[mt][nt][q + 2];
                    s += a + b;
                    sq += a * a + b * b;
                }
#pragma unroll
                for (int off = 4; off < 32; off <<= 1) {
                    s  += __shfl_xor_sync(0xFFFFFFFF, s, off);
                    sq += __shfl_xor_sync(0xFFFFFFFF, sq, off);
                }
                if (gq == 0) {
                    int c = col0 + wc + nt * 8 + tq * 2 + q;
                    atomicAdd(&g_stats[c], s);
                    atomicAdd(&g_stats[256 + c], sq);
                }
            }
        }
    }
}

// ---------------- pool with fused BN+ReLU (batch sorted) ----------------
__global__ void k_pool(const float* __restrict__ Y, const int* __restrict__ batch,
                       int N, int G) {
    int g = blockIdx.x;
    int c = threadIdx.x;
    __shared__ int s_lo, s_hi;
    if (c == 0) {
        int lo = 0, hi = N;
        while (lo < hi) { int m = (lo + hi) >> 1; if (batch[m] < g) lo = m + 1; else hi = m; }
        s_lo = lo;
        int lo2 = lo, hi2 = N;
        while (lo2 < hi2) { int m = (lo2 + hi2) >> 1; if (batch[m] <= g) lo2 = m + 1; else hi2 = m; }
        s_hi = lo2;
    }
    __syncthreads();
    float sc = g_scale[c], sh = g_shift[c];
    float sum = 0.f;
    for (int i = s_lo; i < s_hi; i++)
        sum += fmaxf(0.f, Y[(size_t)i * 256 + c] * sc + sh);
    int cnt = s_hi - s_lo;
    g_pooled[(size_t)g * 256 + c] = tf32r(sum / fmaxf((float)cnt, 1.0f));
}

// ---------------- host launcher ----------------
extern "C" void kernel_launch(void* const* d_in, const int* in_sizes, int n_in,
                              void* d_out, int out_size) {
    const float* x     = (const float*)d_in[0];
    const int*   ei    = (const int*)d_in[1];
    const int*   batch = (const int*)d_in[2];
    const float* W1  = (const float*)d_in[4];
    const float* g1  = (const float*)d_in[6];
    const float* be1 = (const float*)d_in[7];
    const float* W2  = (const float*)d_in[8];
    const float* g2  = (const float*)d_in[10];
    const float* be2 = (const float*)d_in[11];
    const float* W3  = (const float*)d_in[12];
    const float* g3  = (const float*)d_in[14];
    const float* be3 = (const float*)d_in[15];
    const float* Wp  = (const float*)d_in[16];
    const float* bp  = (const float*)d_in[17];
    float* out = (float*)d_out;

    const int N = in_sizes[0] / 9;
    const int E = in_sizes[1] / 2;
    const int G = out_size / 256;
    const int NB = (N + 255) / 256;
    const int SMEM_MMA = 4 * 4608 * 4;

    cudaFuncSetAttribute(k_mma, cudaFuncAttributeMaxDynamicSharedMemorySize, SMEM_MMA);

    void *pA, *pB, *pPooled, *pWt2, *pWt3, *pWtp;
    cudaGetSymbolAddress(&pA, g_bufA);
    cudaGetSymbolAddress(&pB, g_bufB);
    cudaGetSymbolAddress(&pPooled, g_pooled);
    cudaGetSymbolAddress(&pWt2, g_Wt2);
    cudaGetSymbolAddress(&pWt3, g_Wt3);
    cudaGetSymbolAddress(&pWtp, g_Wtp);
    float* bufA = (float*)pA;
    float* bufB = (float*)pB;

    const int* src = ei;
    const int* dst = ei + E;

    // ---- prep ----
    k_zero_trans<<<NB, 256>>>(W2, W3, Wp, N);
    k_deg_accum<<<(E + 255) / 256, 256>>>(dst, E);
    k_dis_self<<<(N + 255) / 256, 256>>>(N);
    k_scan1<<<NB, 256>>>(N);
    k_scan2<<<1, SCAN_NB>>>(NB);
    k_scan3<<<NB, 256>>>(N, E);
    k_csr_fill<<<(E + 255) / 256, 256>>>(src, dst, E);

    // ---- Layer 1 (fused gather + GEMM + stats) ----
    k_layer1<<<(N + 7) / 8, 256>>>(x, W1, bufB, N);
    k_finalize<<<1, 128>>>(g1, be1, N, 128);

    // ---- Layer 2 ----
    k_gather_bn4<128><<<(N + 7) / 8, 256>>>(bufB, bufA, N);
    {
        dim3 grid(2, (N + 127) / 128);
        k_mma<<<grid, 256, SMEM_MMA>>>(bufA, (const float*)pWt2, bufB, N, 128, nullptr, 1);
    }
    k_finalize<<<1, 256>>>(g2, be2, N, 256);

    // ---- Layer 3 ----
    k_gather_bn4<256><<<(N + 3) / 4, 256>>>(bufB, bufA, N);
    {
        dim3 grid(2, (N + 127) / 128);
        k_mma<<<grid, 256, SMEM_MMA>>>(bufA, (const float*)pWt3, bufB, N, 256, nullptr, 1);
    }
    k_finalize<<<1, 256>>>(g3, be3, N, 256);

    // ---- pool + final linear ----
    k_pool<<<G, 256>>>(bufB, batch, N, G);
    {
        dim3 grid(2, (G + 127) / 128);
        k_mma<<<grid, 256, SMEM_MMA>>>((const float*)pPooled, (const float*)pWtp, out,
                                       G, 256, bp, 0);
    }
}